// round 11
// baseline (speedup 1.0000x reference)
#include <cuda_runtime.h>
#include <cuda_fp16.h>
#include <math.h>

#define NMAX 100000
#define EMAX 3200000
#define F_IN 512
#define HID 16
#define NLAB 64

// ---------------- device scratch (no allocations allowed) ----------------
// ONLY referenced inside device code (GB300 ATS silently accepts host-shadow
// addresses — never pass these as kernel args).
// Zero-at-launch invariants (maintained by self-cleaning): g_deg_*, g_lb,
// and all counters are zero when kernel_launch begins.
__device__ float g_norm_src[NMAX];
__device__ float g_norm_dst[NMAX];
__device__ int   g_deg_out[NMAX];
__device__ int   g_deg_in[NMAX];
__device__ int   g_row_start[NMAX];
__device__ unsigned long long g_lb[512];   // scan lookback: (flag<<32)|value
__device__ int   g_csr[EMAX];
__device__ int   g_esrc[EMAX];
__device__ int   g_dslot[EMAX];            // (dst<<13) | slot
__device__ uint2 g_hpreh[NMAX * 4];        // (X@W1) [*ns after scale] fp16 rows
__device__ uint2 g_hmidh[NMAX * 4];        // relu(...)*ns fp16 rows
// completion counters (self-reset at end of each kernel)
__device__ int c_conv, c_scan, c_gemm, c_exit1;
__device__ int c_s1, c_exit2;

// ---------------- helpers ----------------
__device__ __forceinline__ unsigned long long pack2(float v) {
    unsigned long long r;
    asm("mov.b64 %0, {%1, %1};" : "=l"(r) : "f"(v));
    return r;
}
__device__ __forceinline__ void fma2(unsigned long long& acc,
                                     unsigned long long a,
                                     unsigned long long b) {
    asm("fma.rn.f32x2 %0, %1, %2, %0;" : "+l"(acc) : "l"(a), "l"(b));
}
__device__ __forceinline__ float2 unpack2(unsigned long long v) {
    float2 r;
    asm("mov.b64 {%0, %1}, %2;" : "=f"(r.x), "=f"(r.y) : "l"(v));
    return r;
}
__device__ __forceinline__ unsigned h2u(__half2 h) { return *(unsigned*)&h; }
__device__ __forceinline__ uint2 pack_half4(float a, float b, float c, float d) {
    uint2 r;
    r.x = h2u(__floats2half2_rn(a, b));
    r.y = h2u(__floats2half2_rn(c, d));
    return r;
}

// Block-wide wait/signal on a device counter. Progress guarantee: a block
// only ever waits on counters advanced exclusively by LOWER-indexed blocks,
// and CTAs are dispatched in index order.
__device__ __forceinline__ void wait_for(int* ctr, int target) {
    if (threadIdx.x == 0) {
        while (atomicAdd(ctr, 0) < target) __nanosleep(128);
        __threadfence();
    }
    __syncthreads();
}
__device__ __forceinline__ void signal(int* ctr) {
    __syncthreads();
    if (threadIdx.x == 0) { __threadfence(); atomicAdd(ctr, 1); }
}

// ---------------- K1 device parts ----------------

// Per-block edge-dtype probe (32 entries). Order: i64 -> i32 -> f32 -> f64.
__device__ __forceinline__ int probe_fmt(const void* __restrict__ src,
                                         int ecount, int n, int* shflags) {
    int tid = threadIdx.x;
    if (tid < 4) shflags[tid] = 1;
    __syncthreads();
    int nprobe = ecount < 32 ? ecount : 32;
    if (tid < nprobe) {
        long long v64 = ((const long long*)src)[tid];
        if (v64 < 0 || v64 >= (long long)n) atomicAnd(&shflags[0], 0);
        int v32 = ((const int*)src)[tid];
        if (v32 < 0 || v32 >= n) atomicAnd(&shflags[1], 0);
        float f = ((const float*)src)[tid];
        if (!(f >= 0.f && f < (float)n && f == floorf(f))) atomicAnd(&shflags[2], 0);
        double d = ((const double*)src)[tid];
        if (!(d >= 0.0 && d < (double)n && d == floor(d))) atomicAnd(&shflags[3], 0);
    }
    __syncthreads();
    return shflags[0] ? 0 : (shflags[1] ? 1 : (shflags[2] ? 2 : 3));
}

__device__ __forceinline__ void convdeg_part(const void* __restrict__ src,
                                             const void* __restrict__ dst,
                                             int fmt, int e, int ecount, int n) {
    if (e >= ecount) return;   // safe: no block-sync below this in caller path
    int s, d;
    if (fmt == 0) {
        s = (int)__ldcs((const long long*)src + e);
        d = (int)__ldcs((const long long*)dst + e);
    } else if (fmt == 1) {
        s = __ldcs((const int*)src + e);
        d = __ldcs((const int*)dst + e);
    } else if (fmt == 2) {
        s = (int)__ldcs((const float*)src + e);
        d = (int)__ldcs((const float*)dst + e);
    } else {
        s = (int)__ldcs((const double*)src + e);
        d = (int)__ldcs((const double*)dst + e);
    }
    s = s < 0 ? 0 : (s >= n ? n - 1 : s);
    d = d < 0 ? 0 : (d >= n ? n - 1 : d);
    g_esrc[e] = s;
    atomicAdd(&g_deg_out[s], 1);
    int slot = atomicAdd(&g_deg_in[d], 1);
    slot = slot > 8191 ? 8191 : slot;
    g_dslot[e] = (d << 13) | slot;
}

// decoupled-lookback scan of deg_in + norms + deg cleanup (role-local rb)
__device__ __forceinline__ void scan_part(int rb, int n, int* smisc) {
    int* wsum = smisc;            // [0..7]
    int* bexcl_s = smisc + 8;
    int tid = threadIdx.x, lane = tid & 31, wid = tid >> 5;
    int i = rb * 256 + tid;
    int v = (i < n) ? g_deg_in[i] : 0;
    int s = v;
    #pragma unroll
    for (int off = 1; off < 32; off <<= 1) {
        int t = __shfl_up_sync(0xffffffff, s, off);
        if (lane >= off) s += t;
    }
    if (lane == 31) wsum[wid] = s;
    __syncthreads();

    if (wid == 0) {
        int w = (lane < 8) ? wsum[lane] : 0;
        #pragma unroll
        for (int off = 1; off < 8; off <<= 1) {
            int t = __shfl_up_sync(0xffffffff, w, off);
            if (lane >= off) w += t;
        }
        if (lane < 8) wsum[lane] = w;
        int T = __shfl_sync(0xffffffff, w, 7);

        if (lane == 0) {
            unsigned long long pk =
                ((unsigned long long)((rb == 0) ? 2u : 1u) << 32) | (unsigned)T;
            *((volatile unsigned long long*)&g_lb[rb]) = pk;
        }
        int running = 0;
        if (rb > 0) {
            int tile = rb - 1;
            while (true) {
                int idx = tile - lane;
                int flag, val;
                if (idx >= 0) {
                    unsigned long long x;
                    do {
                        x = *((volatile unsigned long long*)&g_lb[idx]);
                        flag = (int)(x >> 32);
                    } while (flag == 0);
                    val = (int)(unsigned)(x & 0xffffffffull);
                } else { flag = 1; val = 0; }
                unsigned mp = __ballot_sync(0xffffffff, flag == 2);
                if (mp) {
                    int first = __ffs(mp) - 1;
                    int contrib = (lane <= first) ? val : 0;
                    #pragma unroll
                    for (int o = 16; o; o >>= 1)
                        contrib += __shfl_xor_sync(0xffffffff, contrib, o);
                    running += contrib;
                    break;
                } else {
                    int contrib = val;
                    #pragma unroll
                    for (int o = 16; o; o >>= 1)
                        contrib += __shfl_xor_sync(0xffffffff, contrib, o);
                    running += contrib;
                    tile -= 32;
                }
            }
            if (lane == 0) {
                unsigned long long pk = (2ull << 32) | (unsigned)(running + T);
                *((volatile unsigned long long*)&g_lb[rb]) = pk;
            }
        }
        if (lane == 0) *bexcl_s = running;
    }
    __syncthreads();

    int base = *bexcl_s + ((wid > 0) ? wsum[wid - 1] : 0);
    if (i < n) {
        g_row_start[i] = base + s - v;
        int dout = g_deg_out[i]; if (dout < 1) dout = 1;
        int din  = v;            if (din  < 1) din  = 1;
        g_norm_src[i] = rsqrtf((float)dout);
        g_norm_dst[i] = rsqrtf((float)din);
        g_deg_out[i] = 0;   // self-clean
        g_deg_in[i]  = 0;
    }
}

// GEMM1: 1 row/thread, f32x2 FMA, writes fp16 UNSCALED rows
__device__ __forceinline__ void gemm_part(const float* __restrict__ X,
                                          const float* __restrict__ W1,
                                          float* __restrict__ sW1,
                                          int rblk, int n) {
    int tid = threadIdx.x;
    #pragma unroll
    for (int i = tid; i < (F_IN * HID) / 4; i += 256)
        ((float4*)sW1)[i] = ((const float4*)W1)[i];
    __syncthreads();

    int row = rblk * 256 + tid;
    if (row >= n) return;   // after the block-wide syncthreads

    unsigned long long acc[8];
    #pragma unroll
    for (int p = 0; p < 8; p++) acc[p] = 0ull;

    const float4* xb = (const float4*)(X + (size_t)row * F_IN);
    for (int c = 0; c < F_IN / 4; c++) {
        float4 x = __ldcs(xb + c);
        const float xs[4] = {x.x, x.y, x.z, x.w};
        #pragma unroll
        for (int k = 0; k < 4; k++) {
            unsigned long long xp = pack2(xs[k]);
            const unsigned long long* w =
                (const unsigned long long*)&sW1[(4 * c + k) * HID];
            #pragma unroll
            for (int p = 0; p < 8; p++) fma2(acc[p], xp, w[p]);
        }
    }
    #pragma unroll
    for (int p = 0; p < 8; p += 2) {
        float2 a = unpack2(acc[p]);
        float2 b = unpack2(acc[p + 1]);
        g_hpreh[row * 4 + p / 2] = pack_half4(a.x, a.y, b.x, b.y);
    }
}

// ---------------- K1: conv | scan | gemm | csr | scale ----------------
__global__ void __launch_bounds__(256)
k_prep(const float* __restrict__ X, const float* __restrict__ W1,
       const void* __restrict__ src, const void* __restrict__ dst,
       int ecount, int n,
       int B_conv, int B_scan, int B_gemm, int B_csr, int B_scale) {
    __shared__ float sW1[F_IN * HID];   // gemm role (32 KB)
    __shared__ int smisc[16];           // probe flags / scan partials
    int b = blockIdx.x;
    int tid = threadIdx.x;
    int total = B_conv + B_scan + B_gemm + B_csr + B_scale;

    int r1 = B_conv, r2 = r1 + B_scan, r3 = r2 + B_gemm, r4 = r3 + B_csr;

    if (b < r1) {
        int fmt = probe_fmt(src, ecount, n, smisc);
        convdeg_part(src, dst, fmt, b * 256 + tid, ecount, n);
        signal(&c_conv);
    } else if (b < r2) {
        wait_for(&c_conv, B_conv);
        scan_part(b - r1, n, smisc);
        signal(&c_scan);
    } else if (b < r3) {
        gemm_part(X, W1, sW1, b - r2, n);
        signal(&c_gemm);
    } else if (b < r4) {
        wait_for(&c_scan, B_scan);
        int e = (b - r3) * 256 + tid;
        if (e < ecount) {
            int ps = __ldcs(&g_dslot[e]);
            int s  = __ldcs(&g_esrc[e]);
            g_csr[g_row_start[ps >> 13] + (ps & 8191)] = s;
        }
    } else {
        wait_for(&c_scan, B_scan);
        wait_for(&c_gemm, B_gemm);
        int i = (b - r4) * 256 + tid;    // uint2 index
        if (i < n * 4) {
            float ns = g_norm_src[i >> 2];
            uint2 q = g_hpreh[i];
            float2 f0 = __half22float2(*(__half2*)&q.x);
            float2 f1 = __half22float2(*(__half2*)&q.y);
            g_hpreh[i] = pack_half4(f0.x * ns, f0.y * ns, f1.x * ns, f1.y * ns);
        }
    }

    // exit protocol: last block out resets all launch-scoped state
    __syncthreads();
    if (tid == 0) {
        __threadfence();
        if (atomicAdd(&c_exit1, 1) == total - 1) {
            c_conv = 0; c_scan = 0; c_gemm = 0;
            for (int i = 0; i < 512; i++) g_lb[i] = 0ull;
            __threadfence();
            c_exit1 = 0;
        }
    }
}

// ---------------- K2 device part: paired gather-sum ----------------
__device__ __forceinline__ void gather_sum(const uint2* __restrict__ table,
                                           int v, int n, int ecount, int lane,
                                           float& ax, float& ay,
                                           float& az, float& aw) {
    int sub = lane & 3;
    int grp = lane >> 2;
    int start = g_row_start[v];
    int end = (v + 1 < n) ? g_row_start[v + 1] : ecount;
    int main_end = start + ((end - start) & ~15);

    ax = ay = az = aw = 0.f;
    for (int e = start + 2 * grp; e < main_end; e += 16) {
        int s0 = __ldg(&g_csr[e]);
        int s1 = __ldg(&g_csr[e + 1]);
        uint2 q0 = __ldg(table + s0 * 4 + sub);
        uint2 q1 = __ldg(table + s1 * 4 + sub);
        __half2 h0 = __hadd2(*(__half2*)&q0.x, *(__half2*)&q1.x);
        __half2 h1 = __hadd2(*(__half2*)&q0.y, *(__half2*)&q1.y);
        float2 f0 = __half22float2(h0);
        float2 f1 = __half22float2(h1);
        ax += f0.x; ay += f0.y; az += f1.x; aw += f1.y;
    }
    for (int e = main_end + grp; e < end; e += 8) {
        int s0 = __ldg(&g_csr[e]);
        uint2 q0 = __ldg(table + s0 * 4 + sub);
        float2 f0 = __half22float2(*(__half2*)&q0.x);
        float2 f1 = __half22float2(*(__half2*)&q0.y);
        ax += f0.x; ay += f0.y; az += f1.x; aw += f1.y;
    }
    #pragma unroll
    for (int off = 4; off < 32; off <<= 1) {
        ax += __shfl_xor_sync(0xffffffff, ax, off);
        ay += __shfl_xor_sync(0xffffffff, ay, off);
        az += __shfl_xor_sync(0xffffffff, az, off);
        aw += __shfl_xor_sync(0xffffffff, aw, off);
    }
}

// ---------------- K2: spmm1 | spmm2+gemm2 ----------------
__global__ void __launch_bounds__(256)
k_net(const float* __restrict__ b1, const float* __restrict__ W2,
      const float* __restrict__ b2, float* __restrict__ out,
      int n, int ecount, int B_s1, int B_s2) {
    __shared__ float sW2[HID * NLAB];
    __shared__ float sb2[NLAB];
    int b = blockIdx.x;
    int tid = threadIdx.x;
    int lane = tid & 31;
    int total = B_s1 + B_s2;

    if (b < B_s1) {
        int v = b * 8 + (tid >> 5);
        if (v < n) {
            float ax, ay, az, aw;
            gather_sum(g_hpreh, v, n, ecount, lane, ax, ay, az, aw);
            if (lane < 4) {
                float nd = g_norm_dst[v];
                float ns = g_norm_src[v];
                float4 bb = ((const float4*)b1)[lane];
                float rx = fmaxf(ax * nd + bb.x, 0.f) * ns;
                float ry = fmaxf(ay * nd + bb.y, 0.f) * ns;
                float rz = fmaxf(az * nd + bb.z, 0.f) * ns;
                float rw = fmaxf(aw * nd + bb.w, 0.f) * ns;
                g_hmidh[v * 4 + lane] = pack_half4(rx, ry, rz, rw);
            }
        }
        signal(&c_s1);
    } else {
        wait_for(&c_s1, B_s1);
        for (int i = tid; i < HID * NLAB; i += 256) sW2[i] = W2[i];
        if (tid < NLAB) sb2[tid] = b2[tid];
        __syncthreads();

        int v = (b - B_s1) * 8 + (tid >> 5);
        if (v < n) {
            float ax, ay, az, aw;
            gather_sum(g_hmidh, v, n, ecount, lane, ax, ay, az, aw);
            float nd = g_norm_dst[v];
            float h[HID];
            #pragma unroll
            for (int j = 0; j < 4; j++) {
                h[4 * j + 0] = __shfl_sync(0xffffffff, ax, j) * nd;
                h[4 * j + 1] = __shfl_sync(0xffffffff, ay, j) * nd;
                h[4 * j + 2] = __shfl_sync(0xffffffff, az, j) * nd;
                h[4 * j + 3] = __shfl_sync(0xffffffff, aw, j) * nd;
            }
            float acc0 = sb2[lane];
            float acc1 = sb2[lane + 32];
            #pragma unroll
            for (int k = 0; k < HID; k++) {
                acc0 += h[k] * sW2[k * NLAB + lane];
                acc1 += h[k] * sW2[k * NLAB + lane + 32];
            }
            out[v * NLAB + lane]      = acc0;
            out[v * NLAB + lane + 32] = acc1;
        }
    }

    __syncthreads();
    if (tid == 0) {
        __threadfence();
        if (atomicAdd(&c_exit2, 1) == total - 1) {
            c_s1 = 0;
            __threadfence();
            c_exit2 = 0;
        }
    }
}

// ---------------- launch ----------------
extern "C" void kernel_launch(void* const* d_in, const int* in_sizes, int n_in,
                              void* d_out, int out_size) {
    int n = out_size / NLAB;
    if (n > NMAX) n = NMAX;

    // Identify inputs by element-count signature.
    int idx_X = -1, idx_W1 = -1, idx_b1 = -1, idx_W2 = -1, idx_b2 = -1;
    int idx_e1 = -1, idx_e2 = -1;
    for (int i = 0; i < n_in; i++) {
        int sz = in_sizes[i];
        if (sz == n * F_IN)            idx_X = i;
        else if (sz == F_IN * HID)     idx_W1 = i;
        else if (sz == HID)            idx_b1 = i;
        else if (sz == HID * NLAB)     idx_W2 = i;
        else if (sz == NLAB)           idx_b2 = i;
        else if (idx_e1 < 0)           idx_e1 = i;
        else                           idx_e2 = i;
    }

    // src/dst by ordering convention (see round-3 notes).
    int idx_src, idx_dst;
    if (idx_e1 > idx_X) { idx_src = idx_e1; idx_dst = idx_e2; }
    else                { idx_dst = idx_e1; idx_src = idx_e2; }

    const float* X   = (const float*)d_in[idx_X];
    const float* W1  = (const float*)d_in[idx_W1];
    const float* b1  = (const float*)d_in[idx_b1];
    const float* W2  = (const float*)d_in[idx_W2];
    const float* b2  = (const float*)d_in[idx_b2];
    const void*  esrc = d_in[idx_src];
    const void*  edst = d_in[idx_dst];

    int ecount = in_sizes[idx_src];
    if (ecount > EMAX) ecount = EMAX;

    int B_conv  = (ecount + 255) / 256;
    int B_scan  = (n + 255) / 256;
    int B_gemm  = (n + 255) / 256;
    int B_csr   = (ecount + 255) / 256;
    int B_scale = (n * 4 + 255) / 256;
    int K1 = B_conv + B_scan + B_gemm + B_csr + B_scale;

    int B_s1 = (n * 32 + 255) / 256;   // warp per node
    int B_s2 = B_s1;
    int K2 = B_s1 + B_s2;

    k_prep<<<K1, 256>>>(X, W1, esrc, edst, ecount, n,
                        B_conv, B_scan, B_gemm, B_csr, B_scale);
    k_net<<<K2, 256>>>(b1, W2, b2, (float*)d_out, n, ecount, B_s1, B_s2);
}

// round 12
// speedup vs baseline: 1.7021x; 1.7021x over previous
#include <cuda_runtime.h>
#include <cuda_fp16.h>
#include <math.h>

#define NMAX 100000
#define EMAX 3200000
#define F_IN 512
#define HID 16
#define NLAB 64

// ---------------- device scratch (no allocations allowed) ----------------
// ONLY referenced inside device code (GB300 ATS silently accepts host-shadow
// addresses — never pass these as kernel args).
// Zero-at-launch invariants (self-cleaning): g_deg_*, g_lb are zero when
// kernel_launch begins (k_scan / k_fused2 re-zero them each launch).
__device__ float g_norm_src[NMAX];
__device__ float g_norm_dst[NMAX];
__device__ int   g_deg_out[NMAX];
__device__ int   g_deg_in[NMAX];
__device__ int   g_row_start[NMAX];
__device__ unsigned long long g_lb[512];   // scan lookback: (flag<<32)|value
__device__ int   g_csr[EMAX];              // BYTE offsets (src*32)
__device__ int   g_dslot[EMAX];            // (dst<<13) | slot
__device__ float g_hpre[NMAX * HID];       // X @ W1 (fp32, unscaled)
__device__ uint2 g_hpreh[NMAX * 4];        // (X@W1)*ns fp16 rows (32B)
__device__ uint2 g_hmidh[NMAX * 4];        // relu(...)*ns fp16 rows (32B)

// ---------------- helpers ----------------
__device__ __forceinline__ unsigned long long pack2(float v) {
    unsigned long long r;
    asm("mov.b64 %0, {%1, %1};" : "=l"(r) : "f"(v));
    return r;
}
__device__ __forceinline__ void fma2(unsigned long long& acc,
                                     unsigned long long a,
                                     unsigned long long b) {
    asm("fma.rn.f32x2 %0, %1, %2, %0;" : "+l"(acc) : "l"(a), "l"(b));
}
__device__ __forceinline__ float2 unpack2(unsigned long long v) {
    float2 r;
    asm("mov.b64 {%0, %1}, %2;" : "=f"(r.x), "=f"(r.y) : "l"(v));
    return r;
}
__device__ __forceinline__ unsigned h2u(__half2 h) { return *(unsigned*)&h; }
__device__ __forceinline__ __half2 u2h(unsigned u) { return *(__half2*)&u; }
__device__ __forceinline__ uint2 pack_half4(float a, float b, float c, float d) {
    uint2 r;
    r.x = h2u(__floats2half2_rn(a, b));
    r.y = h2u(__floats2half2_rn(c, d));
    return r;
}

// Per-block edge-dtype probe (32 entries). Order: i64 -> i32 -> f32 -> f64.
__device__ __forceinline__ int probe_fmt(const void* __restrict__ src,
                                         int ecount, int n, int* shflags) {
    int tid = threadIdx.x;
    if (tid < 4) shflags[tid] = 1;
    __syncthreads();
    int nprobe = ecount < 32 ? ecount : 32;
    if (tid < nprobe) {
        long long v64 = ((const long long*)src)[tid];
        if (v64 < 0 || v64 >= (long long)n) atomicAnd(&shflags[0], 0);
        int v32 = ((const int*)src)[tid];
        if (v32 < 0 || v32 >= n) atomicAnd(&shflags[1], 0);
        float f = ((const float*)src)[tid];
        if (!(f >= 0.f && f < (float)n && f == floorf(f))) atomicAnd(&shflags[2], 0);
        double d = ((const double*)src)[tid];
        if (!(d >= 0.0 && d < (double)n && d == floor(d))) atomicAnd(&shflags[3], 0);
    }
    __syncthreads();
    return shflags[0] ? 0 : (shflags[1] ? 1 : (shflags[2] ? 2 : 3));
}

__device__ __forceinline__ int load_idx(const void* __restrict__ p, int fmt,
                                        int e, int n) {
    int v;
    if (fmt == 0)      v = (int)__ldcs((const long long*)p + e);
    else if (fmt == 1) v = __ldcs((const int*)p + e);
    else if (fmt == 2) v = (int)__ldcs((const float*)p + e);
    else               v = (int)__ldcs((const double*)p + e);
    return v < 0 ? 0 : (v >= n ? n - 1 : v);
}

// ---------------- fused 1: gemm1 (blocks first) || conv+degree ----------------

// GEMM1 (UNSCALED fp32): 2 rows/thread, packed f32x2 FMA, W1 in smem.
__device__ __forceinline__ void gemm1_part(const float* __restrict__ X,
                                           const float* __restrict__ W1,
                                           float* __restrict__ sW1,
                                           int gblk, int n) {
    int tid = threadIdx.x;  // 256
    #pragma unroll
    for (int i = tid; i < (F_IN * HID) / 4; i += 256)
        ((float4*)sW1)[i] = ((const float4*)W1)[i];
    __syncthreads();

    int row0 = gblk * 512 + tid;
    int row1 = row0 + 256;
    if (row0 >= n) return;
    bool has1 = (row1 < n);
    int row1c = has1 ? row1 : row0;

    unsigned long long acc0[8], acc1[8];
    #pragma unroll
    for (int p = 0; p < 8; p++) { acc0[p] = 0ull; acc1[p] = 0ull; }

    const float4* xb0 = (const float4*)(X + (size_t)row0 * F_IN);
    const float4* xb1 = (const float4*)(X + (size_t)row1c * F_IN);

    for (int c = 0; c < F_IN / 4; c++) {
        float4 x0 = __ldcs(xb0 + c);
        float4 x1 = __ldcs(xb1 + c);
        const float xs0[4] = {x0.x, x0.y, x0.z, x0.w};
        const float xs1[4] = {x1.x, x1.y, x1.z, x1.w};
        #pragma unroll
        for (int k = 0; k < 4; k++) {
            unsigned long long xp0 = pack2(xs0[k]);
            unsigned long long xp1 = pack2(xs1[k]);
            const unsigned long long* w =
                (const unsigned long long*)&sW1[(4 * c + k) * HID];
            #pragma unroll
            for (int p = 0; p < 8; p++) {
                unsigned long long wp = w[p];
                fma2(acc0[p], xp0, wp);
                fma2(acc1[p], xp1, wp);
            }
        }
    }

    float* o0 = g_hpre + row0 * HID;
    #pragma unroll
    for (int p = 0; p < 8; p += 2) {
        float2 a = unpack2(acc0[p]);
        float2 b = unpack2(acc0[p + 1]);
        *(float4*)(o0 + 2 * p) = make_float4(a.x, a.y, b.x, b.y);
    }
    if (has1) {
        float* o1 = g_hpre + row1 * HID;
        #pragma unroll
        for (int p = 0; p < 8; p += 2) {
            float2 a = unpack2(acc1[p]);
            float2 b = unpack2(acc1[p + 1]);
            *(float4*)(o1 + 2 * p) = make_float4(a.x, a.y, b.x, b.y);
        }
    }
}

__global__ void __launch_bounds__(256)
k_fused1(const float* __restrict__ X, const float* __restrict__ W1,
         const void* __restrict__ src, const void* __restrict__ dst,
         int ecount, int n, int gemm_blocks) {
    __shared__ float sW1[F_IN * HID];   // gemm role (32 KB)
    __shared__ int shflags[4];
    if ((int)blockIdx.x < gemm_blocks) {
        gemm1_part(X, W1, sW1, blockIdx.x, n);
    } else {
        int fmt = probe_fmt(src, ecount, n, shflags);
        int e = (blockIdx.x - gemm_blocks) * 256 + threadIdx.x;
        if (e < ecount) {
            int s = load_idx(src, fmt, e, n);
            int d = load_idx(dst, fmt, e, n);
            atomicAdd(&g_deg_out[s], 1);
            int slot = atomicAdd(&g_deg_in[d], 1);
            slot = slot > 8191 ? 8191 : slot;
            g_dslot[e] = (d << 13) | slot;
        }
    }
}

// ---------------- single-pass scan (decoupled lookback) + norms + cleanup ----------------
__global__ void __launch_bounds__(256) k_scan(int n) {
    __shared__ int wsum[8];
    __shared__ int bexcl_s;
    int tid = threadIdx.x, lane = tid & 31, wid = tid >> 5;
    int b = blockIdx.x;
    int i = b * 256 + tid;
    int v = (i < n) ? g_deg_in[i] : 0;
    int s = v;
    #pragma unroll
    for (int off = 1; off < 32; off <<= 1) {
        int t = __shfl_up_sync(0xffffffff, s, off);
        if (lane >= off) s += t;
    }
    if (lane == 31) wsum[wid] = s;
    __syncthreads();

    if (wid == 0) {
        int w = (lane < 8) ? wsum[lane] : 0;
        #pragma unroll
        for (int off = 1; off < 8; off <<= 1) {
            int t = __shfl_up_sync(0xffffffff, w, off);
            if (lane >= off) w += t;
        }
        if (lane < 8) wsum[lane] = w;
        int T = __shfl_sync(0xffffffff, w, 7);

        if (lane == 0) {
            unsigned long long pk =
                ((unsigned long long)((b == 0) ? 2u : 1u) << 32) | (unsigned)T;
            *((volatile unsigned long long*)&g_lb[b]) = pk;
        }
        int running = 0;
        if (b > 0) {
            int tile = b - 1;
            while (true) {
                int idx = tile - lane;
                int flag, val;
                if (idx >= 0) {
                    unsigned long long x;
                    do {
                        x = *((volatile unsigned long long*)&g_lb[idx]);
                        flag = (int)(x >> 32);
                    } while (flag == 0);
                    val = (int)(unsigned)(x & 0xffffffffull);
                } else { flag = 1; val = 0; }
                unsigned mp = __ballot_sync(0xffffffff, flag == 2);
                if (mp) {
                    int first = __ffs(mp) - 1;
                    int contrib = (lane <= first) ? val : 0;
                    #pragma unroll
                    for (int o = 16; o; o >>= 1)
                        contrib += __shfl_xor_sync(0xffffffff, contrib, o);
                    running += contrib;
                    break;
                } else {
                    int contrib = val;
                    #pragma unroll
                    for (int o = 16; o; o >>= 1)
                        contrib += __shfl_xor_sync(0xffffffff, contrib, o);
                    running += contrib;
                    tile -= 32;
                }
            }
            if (lane == 0) {
                unsigned long long pk = (2ull << 32) | (unsigned)(running + T);
                *((volatile unsigned long long*)&g_lb[b]) = pk;
            }
        }
        if (lane == 0) bexcl_s = running;
    }
    __syncthreads();

    int base = bexcl_s + ((wid > 0) ? wsum[wid - 1] : 0);
    if (i < n) {
        g_row_start[i] = base + s - v;
        int dout = g_deg_out[i]; if (dout < 1) dout = 1;
        int din  = v;            if (din  < 1) din  = 1;
        g_norm_src[i] = rsqrtf((float)dout);
        g_norm_dst[i] = rsqrtf((float)din);
        g_deg_out[i] = 0;   // self-clean for next replay
        g_deg_in[i]  = 0;
    }
}

// ---------------- fused 2: csr fill (byte offsets) || scale+fp16 || lb clean ----------------
__global__ void __launch_bounds__(256)
k_fused2(const void* __restrict__ src, int ecount, int n, int csr_blocks) {
    __shared__ int shflags[4];
    if ((int)blockIdx.x < csr_blocks) {
        int fmt = probe_fmt(src, ecount, n, shflags);
        int e = blockIdx.x * 256 + threadIdx.x;
        if (e < ecount) {
            int s  = load_idx(src, fmt, e, n);
            int ps = __ldcs(&g_dslot[e]);
            g_csr[g_row_start[ps >> 13] + (ps & 8191)] = s << 5;  // byte offset
        }
    } else {
        int bi = blockIdx.x - csr_blocks;
        int i = bi * 256 + threadIdx.x;       // float4/uint2 row-quarter index
        if (bi < 2 && i < 512) g_lb[i] = 0ull;   // self-clean for next replay
        if (i < n * 4) {
            float ns = g_norm_src[i >> 2];
            float4 v = __ldcs((const float4*)g_hpre + i);
            g_hpreh[i] = pack_half4(v.x * ns, v.y * ns, v.z * ns, v.w * ns);
        }
    }
}

// ---------------- gather-sum: quad-unrolled, byte-offset csr ----------------
__device__ __forceinline__ void gather_sum(const uint2* __restrict__ table,
                                           int v, int n, int ecount, int lane,
                                           float& ax, float& ay,
                                           float& az, float& aw) {
    int sub = lane & 3;
    int grp = lane >> 2;
    int start = g_row_start[v];
    int end = (v + 1 < n) ? g_row_start[v + 1] : ecount;
    int deg = end - start;
    int main_end = start + (deg & ~31);
    const char* tbl = (const char*)table + sub * 8;

    ax = ay = az = aw = 0.f;
    // quad loop: warp consumes 32 consecutive csr entries per iteration
    for (int e = start + 4 * grp; e < main_end; e += 32) {
        int o0 = __ldg(&g_csr[e]);
        int o1 = __ldg(&g_csr[e + 1]);
        int o2 = __ldg(&g_csr[e + 2]);
        int o3 = __ldg(&g_csr[e + 3]);
        uint2 q0 = *(const uint2*)(tbl + o0);
        uint2 q1 = *(const uint2*)(tbl + o1);
        uint2 q2 = *(const uint2*)(tbl + o2);
        uint2 q3 = *(const uint2*)(tbl + o3);
        __half2 hx0 = __hadd2(u2h(q0.x), u2h(q1.x));
        __half2 hx1 = __hadd2(u2h(q2.x), u2h(q3.x));
        __half2 hy0 = __hadd2(u2h(q0.y), u2h(q1.y));
        __half2 hy1 = __hadd2(u2h(q2.y), u2h(q3.y));
        float2 f0 = __half22float2(hx0);
        float2 f1 = __half22float2(hx1);
        float2 g0 = __half22float2(hy0);
        float2 g1 = __half22float2(hy1);
        ax += f0.x + f1.x; ay += f0.y + f1.y;
        az += g0.x + g1.x; aw += g0.y + g1.y;
    }
    // tail: one edge per group
    for (int e = main_end + grp; e < end; e += 8) {
        int o0 = __ldg(&g_csr[e]);
        uint2 q0 = *(const uint2*)(tbl + o0);
        float2 f0 = __half22float2(u2h(q0.x));
        float2 g0 = __half22float2(u2h(q0.y));
        ax += f0.x; ay += f0.y; az += g0.x; aw += g0.y;
    }
    #pragma unroll
    for (int off = 4; off < 32; off <<= 1) {
        ax += __shfl_xor_sync(0xffffffff, ax, off);
        ay += __shfl_xor_sync(0xffffffff, ay, off);
        az += __shfl_xor_sync(0xffffffff, az, off);
        aw += __shfl_xor_sync(0xffffffff, aw, off);
    }
}

// ---------------- SpMM stage 1 ----------------
__global__ void __launch_bounds__(256)
k_spmm1(const float* __restrict__ b1, int n, int ecount) {
    int v = (blockIdx.x * 256 + threadIdx.x) >> 5;
    if (v >= n) return;
    int lane = threadIdx.x & 31;
    float ax, ay, az, aw;
    gather_sum(g_hpreh, v, n, ecount, lane, ax, ay, az, aw);
    if (lane < 4) {
        float nd = g_norm_dst[v];
        float ns = g_norm_src[v];
        float4 bb = ((const float4*)b1)[lane];
        float rx = fmaxf(ax * nd + bb.x, 0.f) * ns;
        float ry = fmaxf(ay * nd + bb.y, 0.f) * ns;
        float rz = fmaxf(az * nd + bb.z, 0.f) * ns;
        float rw = fmaxf(aw * nd + bb.w, 0.f) * ns;
        g_hmidh[v * 4 + lane] = pack_half4(rx, ry, rz, rw);
    }
}

// ---------------- SpMM stage 2 + GEMM2 fused ----------------
__global__ void __launch_bounds__(256)
k_spmm2g2(const float* __restrict__ W2, const float* __restrict__ b2,
          float* __restrict__ out, int n, int ecount) {
    __shared__ float sW2[HID * NLAB];
    __shared__ float sb2[NLAB];
    int tid = threadIdx.x;  // 256
    for (int i = tid; i < HID * NLAB; i += 256) sW2[i] = W2[i];
    if (tid < NLAB) sb2[tid] = b2[tid];
    __syncthreads();

    int v = (blockIdx.x * 256 + tid) >> 5;
    if (v >= n) return;
    int lane = tid & 31;
    float ax, ay, az, aw;
    gather_sum(g_hmidh, v, n, ecount, lane, ax, ay, az, aw);

    float nd = g_norm_dst[v];
    float h[HID];
    #pragma unroll
    for (int j = 0; j < 4; j++) {
        h[4 * j + 0] = __shfl_sync(0xffffffff, ax, j) * nd;
        h[4 * j + 1] = __shfl_sync(0xffffffff, ay, j) * nd;
        h[4 * j + 2] = __shfl_sync(0xffffffff, az, j) * nd;
        h[4 * j + 3] = __shfl_sync(0xffffffff, aw, j) * nd;
    }
    float acc0 = sb2[lane];
    float acc1 = sb2[lane + 32];
    #pragma unroll
    for (int k = 0; k < HID; k++) {
        acc0 += h[k] * sW2[k * NLAB + lane];
        acc1 += h[k] * sW2[k * NLAB + lane + 32];
    }
    out[v * NLAB + lane]      = acc0;
    out[v * NLAB + lane + 32] = acc1;
}

// ---------------- launch ----------------
extern "C" void kernel_launch(void* const* d_in, const int* in_sizes, int n_in,
                              void* d_out, int out_size) {
    int n = out_size / NLAB;
    if (n > NMAX) n = NMAX;

    // Identify inputs by element-count signature.
    int idx_X = -1, idx_W1 = -1, idx_b1 = -1, idx_W2 = -1, idx_b2 = -1;
    int idx_e1 = -1, idx_e2 = -1;
    for (int i = 0; i < n_in; i++) {
        int sz = in_sizes[i];
        if (sz == n * F_IN)            idx_X = i;
        else if (sz == F_IN * HID)     idx_W1 = i;
        else if (sz == HID)            idx_b1 = i;
        else if (sz == HID * NLAB)     idx_W2 = i;
        else if (sz == NLAB)           idx_b2 = i;
        else if (idx_e1 < 0)           idx_e1 = i;
        else                           idx_e2 = i;
    }

    // src/dst by ordering convention (see round-3 notes).
    int idx_src, idx_dst;
    if (idx_e1 > idx_X) { idx_src = idx_e1; idx_dst = idx_e2; }
    else                { idx_dst = idx_e1; idx_src = idx_e2; }

    const float* X   = (const float*)d_in[idx_X];
    const float* W1  = (const float*)d_in[idx_W1];
    const float* b1  = (const float*)d_in[idx_b1];
    const float* W2  = (const float*)d_in[idx_W2];
    const float* b2  = (const float*)d_in[idx_b2];
    const void*  esrc = d_in[idx_src];
    const void*  edst = d_in[idx_dst];

    int ecount = in_sizes[idx_src];
    if (ecount > EMAX) ecount = EMAX;

    int gb256_n = (n + 255) / 256;
    int gb256_e = (ecount + 255) / 256;
    int gemm_blocks = (n + 511) / 512;
    int scale_blocks = (n * 4 + 255) / 256;

    k_fused1<<<gemm_blocks + gb256_e, 256>>>(X, W1, esrc, edst,
                                             ecount, n, gemm_blocks);
    k_scan<<<gb256_n, 256>>>(n);
    k_fused2<<<gb256_e + scale_blocks, 256>>>(esrc, ecount, n, gb256_e);

    int spmm_blocks = (n * 32 + 255) / 256;
    k_spmm1<<<spmm_blocks, 256>>>(b1, n, ecount);
    k_spmm2g2<<<spmm_blocks, 256>>>(W2, b2, (float*)d_out, n, ecount);
}

// round 13
// speedup vs baseline: 1.8322x; 1.0765x over previous
#include <cuda_runtime.h>
#include <cuda_fp16.h>
#include <math.h>

#define NMAX 100000
#define EMAX 3200000
#define F_IN 512
#define HID 16
#define NLAB 64

// ---------------- device scratch (no allocations allowed) ----------------
// ONLY referenced inside device code (GB300 ATS silently accepts host-shadow
// addresses — never pass these as kernel args).
// Zero-at-launch invariants (self-cleaning): g_deg_*, g_lb are zero when
// kernel_launch begins (k_scan / k_fused2 re-zero them each launch).
__device__ float g_norm_src[NMAX];
__device__ float g_norm_dst[NMAX];
__device__ int   g_deg_out[NMAX];
__device__ int   g_deg_in[NMAX];
__device__ int   g_row_start[NMAX];
__device__ unsigned long long g_lb[512];   // scan lookback: (flag<<32)|value
__device__ int   g_csr[EMAX];              // BYTE offsets (src*32)
__device__ int   g_dslot[EMAX];            // (dst<<13) | slot
__device__ uint2 g_hpreh[NMAX * 4];        // (X@W1)[*ns after scale] fp16 rows
__device__ uint2 g_hmidh[NMAX * 4];        // relu(...)*ns fp16 rows

// ---------------- helpers ----------------
__device__ __forceinline__ unsigned long long pack2(float v) {
    unsigned long long r;
    asm("mov.b64 %0, {%1, %1};" : "=l"(r) : "f"(v));
    return r;
}
__device__ __forceinline__ void fma2(unsigned long long& acc,
                                     unsigned long long a,
                                     unsigned long long b) {
    asm("fma.rn.f32x2 %0, %1, %2, %0;" : "+l"(acc) : "l"(a), "l"(b));
}
__device__ __forceinline__ float2 unpack2(unsigned long long v) {
    float2 r;
    asm("mov.b64 {%0, %1}, %2;" : "=f"(r.x), "=f"(r.y) : "l"(v));
    return r;
}
__device__ __forceinline__ unsigned h2u(__half2 h) { return *(unsigned*)&h; }
__device__ __forceinline__ __half2 u2h(unsigned u) { return *(__half2*)&u; }
__device__ __forceinline__ uint2 pack_half4(float a, float b, float c, float d) {
    uint2 r;
    r.x = h2u(__floats2half2_rn(a, b));
    r.y = h2u(__floats2half2_rn(c, d));
    return r;
}

// Per-block edge-dtype probe (32 entries). Order: i64 -> i32 -> f32 -> f64.
__device__ __forceinline__ int probe_fmt(const void* __restrict__ src,
                                         int ecount, int n, int* shflags) {
    int tid = threadIdx.x;
    if (tid < 4) shflags[tid] = 1;
    __syncthreads();
    int nprobe = ecount < 32 ? ecount : 32;
    if (tid < nprobe) {
        long long v64 = ((const long long*)src)[tid];
        if (v64 < 0 || v64 >= (long long)n) atomicAnd(&shflags[0], 0);
        int v32 = ((const int*)src)[tid];
        if (v32 < 0 || v32 >= n) atomicAnd(&shflags[1], 0);
        float f = ((const float*)src)[tid];
        if (!(f >= 0.f && f < (float)n && f == floorf(f))) atomicAnd(&shflags[2], 0);
        double d = ((const double*)src)[tid];
        if (!(d >= 0.0 && d < (double)n && d == floor(d))) atomicAnd(&shflags[3], 0);
    }
    __syncthreads();
    return shflags[0] ? 0 : (shflags[1] ? 1 : (shflags[2] ? 2 : 3));
}

__device__ __forceinline__ int load_idx(const void* __restrict__ p, int fmt,
                                        int e, int n) {
    int v;
    if (fmt == 0)      v = (int)__ldcs((const long long*)p + e);
    else if (fmt == 1) v = __ldcs((const int*)p + e);
    else if (fmt == 2) v = (int)__ldcs((const float*)p + e);
    else               v = (int)__ldcs((const double*)p + e);
    return v < 0 ? 0 : (v >= n ? n - 1 : v);
}

// ---------------- fused 1: gemm1 (blocks first) || conv+degree ----------------

// GEMM1: 2 rows/thread, packed f32x2 FMA, writes fp16 UNSCALED rows.
__device__ __forceinline__ void gemm1_part(const float* __restrict__ X,
                                           const float* __restrict__ W1,
                                           float* __restrict__ sW1,
                                           int gblk, int n) {
    int tid = threadIdx.x;  // 256
    #pragma unroll
    for (int i = tid; i < (F_IN * HID) / 4; i += 256)
        ((float4*)sW1)[i] = ((const float4*)W1)[i];
    __syncthreads();

    int row0 = gblk * 512 + tid;
    int row1 = row0 + 256;
    if (row0 >= n) return;
    bool has1 = (row1 < n);
    int row1c = has1 ? row1 : row0;

    unsigned long long acc0[8], acc1[8];
    #pragma unroll
    for (int p = 0; p < 8; p++) { acc0[p] = 0ull; acc1[p] = 0ull; }

    const float4* xb0 = (const float4*)(X + (size_t)row0 * F_IN);
    const float4* xb1 = (const float4*)(X + (size_t)row1c * F_IN);

    for (int c = 0; c < F_IN / 4; c++) {
        float4 x0 = __ldcs(xb0 + c);
        float4 x1 = __ldcs(xb1 + c);
        const float xs0[4] = {x0.x, x0.y, x0.z, x0.w};
        const float xs1[4] = {x1.x, x1.y, x1.z, x1.w};
        #pragma unroll
        for (int k = 0; k < 4; k++) {
            unsigned long long xp0 = pack2(xs0[k]);
            unsigned long long xp1 = pack2(xs1[k]);
            const unsigned long long* w =
                (const unsigned long long*)&sW1[(4 * c + k) * HID];
            #pragma unroll
            for (int p = 0; p < 8; p++) {
                unsigned long long wp = w[p];
                fma2(acc0[p], xp0, wp);
                fma2(acc1[p], xp1, wp);
            }
        }
    }

    #pragma unroll
    for (int p = 0; p < 8; p += 2) {
        float2 a = unpack2(acc0[p]);
        float2 b = unpack2(acc0[p + 1]);
        g_hpreh[row0 * 4 + p / 2] = pack_half4(a.x, a.y, b.x, b.y);
    }
    if (has1) {
        #pragma unroll
        for (int p = 0; p < 8; p += 2) {
            float2 a = unpack2(acc1[p]);
            float2 b = unpack2(acc1[p + 1]);
            g_hpreh[row1 * 4 + p / 2] = pack_half4(a.x, a.y, b.x, b.y);
        }
    }
}

__global__ void __launch_bounds__(256)
k_fused1(const float* __restrict__ X, const float* __restrict__ W1,
         const void* __restrict__ src, const void* __restrict__ dst,
         int ecount, int n, int gemm_blocks) {
    __shared__ float sW1[F_IN * HID];   // gemm role (32 KB)
    __shared__ int shflags[4];
    if ((int)blockIdx.x < gemm_blocks) {
        gemm1_part(X, W1, sW1, blockIdx.x, n);
    } else {
        int fmt = probe_fmt(src, ecount, n, shflags);
        int e = (blockIdx.x - gemm_blocks) * 256 + threadIdx.x;
        if (e < ecount) {
            int s = load_idx(src, fmt, e, n);
            int d = load_idx(dst, fmt, e, n);
            atomicAdd(&g_deg_out[s], 1);
            int slot = atomicAdd(&g_deg_in[d], 1);
            slot = slot > 8191 ? 8191 : slot;
            g_dslot[e] = (d << 13) | slot;
        }
    }
}

// ---------------- single-pass scan (decoupled lookback) + norms + cleanup ----------------
__global__ void __launch_bounds__(256) k_scan(int n) {
    __shared__ int wsum[8];
    __shared__ int bexcl_s;
    int tid = threadIdx.x, lane = tid & 31, wid = tid >> 5;
    int b = blockIdx.x;
    int i = b * 256 + tid;
    int v = (i < n) ? g_deg_in[i] : 0;
    int s = v;
    #pragma unroll
    for (int off = 1; off < 32; off <<= 1) {
        int t = __shfl_up_sync(0xffffffff, s, off);
        if (lane >= off) s += t;
    }
    if (lane == 31) wsum[wid] = s;
    __syncthreads();

    if (wid == 0) {
        int w = (lane < 8) ? wsum[lane] : 0;
        #pragma unroll
        for (int off = 1; off < 8; off <<= 1) {
            int t = __shfl_up_sync(0xffffffff, w, off);
            if (lane >= off) w += t;
        }
        if (lane < 8) wsum[lane] = w;
        int T = __shfl_sync(0xffffffff, w, 7);

        if (lane == 0) {
            unsigned long long pk =
                ((unsigned long long)((b == 0) ? 2u : 1u) << 32) | (unsigned)T;
            *((volatile unsigned long long*)&g_lb[b]) = pk;
        }
        int running = 0;
        if (b > 0) {
            int tile = b - 1;
            while (true) {
                int idx = tile - lane;
                int flag, val;
                if (idx >= 0) {
                    unsigned long long x;
                    do {
                        x = *((volatile unsigned long long*)&g_lb[idx]);
                        flag = (int)(x >> 32);
                    } while (flag == 0);
                    val = (int)(unsigned)(x & 0xffffffffull);
                } else { flag = 1; val = 0; }
                unsigned mp = __ballot_sync(0xffffffff, flag == 2);
                if (mp) {
                    int first = __ffs(mp) - 1;
                    int contrib = (lane <= first) ? val : 0;
                    #pragma unroll
                    for (int o = 16; o; o >>= 1)
                        contrib += __shfl_xor_sync(0xffffffff, contrib, o);
                    running += contrib;
                    break;
                } else {
                    int contrib = val;
                    #pragma unroll
                    for (int o = 16; o; o >>= 1)
                        contrib += __shfl_xor_sync(0xffffffff, contrib, o);
                    running += contrib;
                    tile -= 32;
                }
            }
            if (lane == 0) {
                unsigned long long pk = (2ull << 32) | (unsigned)(running + T);
                *((volatile unsigned long long*)&g_lb[b]) = pk;
            }
        }
        if (lane == 0) bexcl_s = running;
    }
    __syncthreads();

    int base = bexcl_s + ((wid > 0) ? wsum[wid - 1] : 0);
    if (i < n) {
        g_row_start[i] = base + s - v;
        int dout = g_deg_out[i]; if (dout < 1) dout = 1;
        int din  = v;            if (din  < 1) din  = 1;
        g_norm_src[i] = rsqrtf((float)dout);
        g_norm_dst[i] = rsqrtf((float)din);
        g_deg_out[i] = 0;   // self-clean for next replay
        g_deg_in[i]  = 0;
    }
}

// ---------------- fused 2: csr fill (byte offsets) || scale hpreh in place ----------------
__global__ void __launch_bounds__(256)
k_fused2(const void* __restrict__ src, int ecount, int n, int csr_blocks) {
    __shared__ int shflags[4];
    if ((int)blockIdx.x < csr_blocks) {
        int fmt = probe_fmt(src, ecount, n, shflags);
        int e = blockIdx.x * 256 + threadIdx.x;
        if (e < ecount) {
            int s  = load_idx(src, fmt, e, n);
            int ps = __ldcs(&g_dslot[e]);
            g_csr[g_row_start[ps >> 13] + (ps & 8191)] = s << 5;  // byte offset
        }
    } else {
        int bi = blockIdx.x - csr_blocks;
        int i = bi * 256 + threadIdx.x;       // uint2 row-quarter index
        if (bi < 2 && i < 512) g_lb[i] = 0ull;   // self-clean for next replay
        if (i < n * 4) {
            float ns = g_norm_src[i >> 2];
            uint2 q = g_hpreh[i];
            float2 f0 = __half22float2(u2h(q.x));
            float2 f1 = __half22float2(u2h(q.y));
            g_hpreh[i] = pack_half4(f0.x * ns, f0.y * ns, f1.x * ns, f1.y * ns);
        }
    }
}

// ---------------- gather-sum: 2 nodes/warp, 16 lanes/node ----------------
// sub = lane&3 (row quarter), grp = (lane>>2)&3 (edge slot), half = lane>>4.
// Main loop: 4 edges/group/iter = 16 edges/node/iter; tail 1 edge/group.
// Reduce: 2 xor levels (4, 8) serve both half-warps simultaneously.
__device__ __forceinline__ void gather_sum2(const uint2* __restrict__ table,
                                            int start, int end, int lane,
                                            float& ax, float& ay,
                                            float& az, float& aw) {
    int sub = lane & 3;
    int grp = (lane >> 2) & 3;
    int deg = end - start;
    int main_end = start + (deg & ~15);
    const char* tbl = (const char*)table + sub * 8;

    ax = ay = az = aw = 0.f;
    for (int e = start + 4 * grp; e < main_end; e += 16) {
        int o0 = __ldg(&g_csr[e]);
        int o1 = __ldg(&g_csr[e + 1]);
        int o2 = __ldg(&g_csr[e + 2]);
        int o3 = __ldg(&g_csr[e + 3]);
        uint2 q0 = *(const uint2*)(tbl + o0);
        uint2 q1 = *(const uint2*)(tbl + o1);
        uint2 q2 = *(const uint2*)(tbl + o2);
        uint2 q3 = *(const uint2*)(tbl + o3);
        __half2 hx0 = __hadd2(u2h(q0.x), u2h(q1.x));
        __half2 hx1 = __hadd2(u2h(q2.x), u2h(q3.x));
        __half2 hy0 = __hadd2(u2h(q0.y), u2h(q1.y));
        __half2 hy1 = __hadd2(u2h(q2.y), u2h(q3.y));
        float2 f0 = __half22float2(hx0);
        float2 f1 = __half22float2(hx1);
        float2 g0 = __half22float2(hy0);
        float2 g1 = __half22float2(hy1);
        ax += f0.x + f1.x; ay += f0.y + f1.y;
        az += g0.x + g1.x; aw += g0.y + g1.y;
    }
    for (int e = main_end + grp; e < end; e += 4) {
        int o0 = __ldg(&g_csr[e]);
        uint2 q0 = *(const uint2*)(tbl + o0);
        float2 f0 = __half22float2(u2h(q0.x));
        float2 g0 = __half22float2(u2h(q0.y));
        ax += f0.x; ay += f0.y; az += g0.x; aw += g0.y;
    }
    // reduce across the 4 groups within each 16-lane half (offsets 4, 8)
    #pragma unroll
    for (int off = 4; off < 16; off <<= 1) {
        ax += __shfl_xor_sync(0xffffffff, ax, off);
        ay += __shfl_xor_sync(0xffffffff, ay, off);
        az += __shfl_xor_sync(0xffffffff, az, off);
        aw += __shfl_xor_sync(0xffffffff, aw, off);
    }
}

// ---------------- SpMM stage 1 (2 nodes per warp) ----------------
__global__ void __launch_bounds__(256)
k_spmm1(const float* __restrict__ b1, int n, int ecount) {
    int tid = threadIdx.x;
    int lane = tid & 31;
    int w = (blockIdx.x * 256 + tid) >> 5;     // warp index
    int v = 2 * w + (lane >> 4);               // this half-warp's node
    bool active = (v < n);

    int start = 0, end = 0;
    if (active) {
        start = g_row_start[v];
        end = (v + 1 < n) ? g_row_start[v + 1] : ecount;
    }
    float ax, ay, az, aw;
    gather_sum2(g_hpreh, start, end, lane, ax, ay, az, aw);

    if ((lane & 12) == 0 && active) {
        int sub = lane & 3;
        float nd = g_norm_dst[v];
        float ns = g_norm_src[v];
        float4 bb = ((const float4*)b1)[sub];
        float rx = fmaxf(ax * nd + bb.x, 0.f) * ns;
        float ry = fmaxf(ay * nd + bb.y, 0.f) * ns;
        float rz = fmaxf(az * nd + bb.z, 0.f) * ns;
        float rw = fmaxf(aw * nd + bb.w, 0.f) * ns;
        g_hmidh[v * 4 + sub] = pack_half4(rx, ry, rz, rw);
    }
}

// ---------------- SpMM stage 2 + GEMM2 (2 nodes per warp) ----------------
__global__ void __launch_bounds__(256)
k_spmm2g2(const float* __restrict__ W2, const float* __restrict__ b2,
          float* __restrict__ out, int n, int ecount) {
    __shared__ float sW2[HID * NLAB];
    __shared__ float sb2[NLAB];
    int tid = threadIdx.x;  // 256
    for (int i = tid; i < HID * NLAB; i += 256) sW2[i] = W2[i];
    if (tid < NLAB) sb2[tid] = b2[tid];
    __syncthreads();

    int lane = tid & 31;
    int w = (blockIdx.x * 256 + tid) >> 5;
    int v = 2 * w + (lane >> 4);
    bool active = (v < n);

    int start = 0, end = 0;
    if (active) {
        start = g_row_start[v];
        end = (v + 1 < n) ? g_row_start[v + 1] : ecount;
    }
    float ax, ay, az, aw;
    gather_sum2(g_hmidh, start, end, lane, ax, ay, az, aw);

    // broadcast this half's 16 h values (holders: lanes base+0..base+3)
    float nd = active ? g_norm_dst[v] : 0.f;
    int base = lane & 16;
    float h[HID];
    #pragma unroll
    for (int s = 0; s < 4; s++) {
        h[4 * s + 0] = __shfl_sync(0xffffffff, ax, base + s) * nd;
        h[4 * s + 1] = __shfl_sync(0xffffffff, ay, base + s) * nd;
        h[4 * s + 2] = __shfl_sync(0xffffffff, az, base + s) * nd;
        h[4 * s + 3] = __shfl_sync(0xffffffff, aw, base + s) * nd;
    }
    if (!active) return;
    int l16 = lane & 15;
    float acc0 = sb2[l16];
    float acc1 = sb2[l16 + 16];
    float acc2 = sb2[l16 + 32];
    float acc3 = sb2[l16 + 48];
    #pragma unroll
    for (int k = 0; k < HID; k++) {
        float hk = h[k];
        const float* wrow = &sW2[k * NLAB + l16];
        acc0 += hk * wrow[0];
        acc1 += hk * wrow[16];
        acc2 += hk * wrow[32];
        acc3 += hk * wrow[48];
    }
    float* o = out + v * NLAB + l16;
    o[0]  = acc0;
    o[16] = acc1;
    o[32] = acc2;
    o[48] = acc3;
}

// ---------------- launch ----------------
extern "C" void kernel_launch(void* const* d_in, const int* in_sizes, int n_in,
                              void* d_out, int out_size) {
    int n = out_size / NLAB;
    if (n > NMAX) n = NMAX;

    // Identify inputs by element-count signature.
    int idx_X = -1, idx_W1 = -1, idx_b1 = -1, idx_W2 = -1, idx_b2 = -1;
    int idx_e1 = -1, idx_e2 = -1;
    for (int i = 0; i < n_in; i++) {
        int sz = in_sizes[i];
        if (sz == n * F_IN)            idx_X = i;
        else if (sz == F_IN * HID)     idx_W1 = i;
        else if (sz == HID)            idx_b1 = i;
        else if (sz == HID * NLAB)     idx_W2 = i;
        else if (sz == NLAB)           idx_b2 = i;
        else if (idx_e1 < 0)           idx_e1 = i;
        else                           idx_e2 = i;
    }

    // src/dst by ordering convention (see round-3 notes).
    int idx_src, idx_dst;
    if (idx_e1 > idx_X) { idx_src = idx_e1; idx_dst = idx_e2; }
    else                { idx_dst = idx_e1; idx_src = idx_e2; }

    const float* X   = (const float*)d_in[idx_X];
    const float* W1  = (const float*)d_in[idx_W1];
    const float* b1  = (const float*)d_in[idx_b1];
    const float* W2  = (const float*)d_in[idx_W2];
    const float* b2  = (const float*)d_in[idx_b2];
    const void*  esrc = d_in[idx_src];
    const void*  edst = d_in[idx_dst];

    int ecount = in_sizes[idx_src];
    if (ecount > EMAX) ecount = EMAX;

    int gb256_n = (n + 255) / 256;
    int gb256_e = (ecount + 255) / 256;
    int gemm_blocks = (n + 511) / 512;
    int scale_blocks = (n * 4 + 255) / 256;

    k_fused1<<<gemm_blocks + gb256_e, 256>>>(X, W1, esrc, edst,
                                             ecount, n, gemm_blocks);
    k_scan<<<gb256_n, 256>>>(n);
    k_fused2<<<gb256_e + scale_blocks, 256>>>(esrc, ecount, n, gb256_e);

    // 2 nodes per warp -> 16 nodes per 256-thread block
    int spmm_blocks = (n + 15) / 16;
    k_spmm1<<<spmm_blocks, 256>>>(b1, n, ecount);
    k_spmm2g2<<<spmm_blocks, 256>>>(W2, b2, (float*)d_out, n, ecount);
}

// round 14
// speedup vs baseline: 1.8897x; 1.0314x over previous
#include <cuda_runtime.h>
#include <cuda_fp16.h>
#include <math.h>

#define NMAX 100000
#define EMAX 3200000
#define F_IN 512
#define HID 16
#define NLAB 64

// ---------------- device scratch (no allocations allowed) ----------------
// ONLY referenced inside device code (GB300 ATS silently accepts host-shadow
// addresses — never pass these as kernel args).
// Zero-at-launch invariants (self-cleaning): g_deg_*, g_lb are zero when
// kernel_launch begins (k_scan / k_csr re-zero them each launch).
__device__ float g_norm_src[NMAX];
__device__ float g_norm_dst[NMAX];
__device__ int   g_deg_out[NMAX];
__device__ int   g_deg_in[NMAX];
__device__ int   g_row_start[NMAX];
__device__ unsigned long long g_lb[512];   // scan lookback: (flag<<32)|value
__device__ int   g_csr[EMAX];              // BYTE offsets (src*32)
__device__ int   g_dslot[EMAX];            // (dst<<13) | slot
__device__ uint2 g_hpreh[NMAX * 4];        // (X@W1)[*ns after scan] fp16 rows
__device__ uint2 g_hmidh[NMAX * 4];        // relu(...)*ns fp16 rows

// ---------------- helpers ----------------
__device__ __forceinline__ unsigned long long pack2(float v) {
    unsigned long long r;
    asm("mov.b64 %0, {%1, %1};" : "=l"(r) : "f"(v));
    return r;
}
__device__ __forceinline__ void fma2(unsigned long long& acc,
                                     unsigned long long a,
                                     unsigned long long b) {
    asm("fma.rn.f32x2 %0, %1, %2, %0;" : "+l"(acc) : "l"(a), "l"(b));
}
__device__ __forceinline__ float2 unpack2(unsigned long long v) {
    float2 r;
    asm("mov.b64 {%0, %1}, %2;" : "=f"(r.x), "=f"(r.y) : "l"(v));
    return r;
}
__device__ __forceinline__ unsigned h2u(__half2 h) { return *(unsigned*)&h; }
__device__ __forceinline__ __half2 u2h(unsigned u) { return *(__half2*)&u; }
__device__ __forceinline__ uint2 pack_half4(float a, float b, float c, float d) {
    uint2 r;
    r.x = h2u(__floats2half2_rn(a, b));
    r.y = h2u(__floats2half2_rn(c, d));
    return r;
}

// Per-block edge-dtype probe (32 entries). Order: i64 -> i32 -> f32 -> f64.
__device__ __forceinline__ int probe_fmt(const void* __restrict__ src,
                                         int ecount, int n, int* shflags) {
    int tid = threadIdx.x;
    if (tid < 4) shflags[tid] = 1;
    __syncthreads();
    int nprobe = ecount < 32 ? ecount : 32;
    if (tid < nprobe) {
        long long v64 = ((const long long*)src)[tid];
        if (v64 < 0 || v64 >= (long long)n) atomicAnd(&shflags[0], 0);
        int v32 = ((const int*)src)[tid];
        if (v32 < 0 || v32 >= n) atomicAnd(&shflags[1], 0);
        float f = ((const float*)src)[tid];
        if (!(f >= 0.f && f < (float)n && f == floorf(f))) atomicAnd(&shflags[2], 0);
        double d = ((const double*)src)[tid];
        if (!(d >= 0.0 && d < (double)n && d == floor(d))) atomicAnd(&shflags[3], 0);
    }
    __syncthreads();
    return shflags[0] ? 0 : (shflags[1] ? 1 : (shflags[2] ? 2 : 3));
}

__device__ __forceinline__ int load_idx(const void* __restrict__ p, int fmt,
                                        int e, int n) {
    int v;
    if (fmt == 0)      v = (int)__ldcs((const long long*)p + e);
    else if (fmt == 1) v = __ldcs((const int*)p + e);
    else if (fmt == 2) v = (int)__ldcs((const float*)p + e);
    else               v = (int)__ldcs((const double*)p + e);
    return v < 0 ? 0 : (v >= n ? n - 1 : v);
}

// ---------------- fused 1: gemm1 (blocks first) || conv+degree ----------------

// GEMM1: 2 rows/thread, packed f32x2 FMA, writes fp16 UNSCALED rows.
__device__ __forceinline__ void gemm1_part(const float* __restrict__ X,
                                           const float* __restrict__ W1,
                                           float* __restrict__ sW1,
                                           int gblk, int n) {
    int tid = threadIdx.x;  // 256
    #pragma unroll
    for (int i = tid; i < (F_IN * HID) / 4; i += 256)
        ((float4*)sW1)[i] = ((const float4*)W1)[i];
    __syncthreads();

    int row0 = gblk * 512 + tid;
    int row1 = row0 + 256;
    if (row0 >= n) return;
    bool has1 = (row1 < n);
    int row1c = has1 ? row1 : row0;

    unsigned long long acc0[8], acc1[8];
    #pragma unroll
    for (int p = 0; p < 8; p++) { acc0[p] = 0ull; acc1[p] = 0ull; }

    const float4* xb0 = (const float4*)(X + (size_t)row0 * F_IN);
    const float4* xb1 = (const float4*)(X + (size_t)row1c * F_IN);

    for (int c = 0; c < F_IN / 4; c++) {
        float4 x0 = __ldcs(xb0 + c);
        float4 x1 = __ldcs(xb1 + c);
        const float xs0[4] = {x0.x, x0.y, x0.z, x0.w};
        const float xs1[4] = {x1.x, x1.y, x1.z, x1.w};
        #pragma unroll
        for (int k = 0; k < 4; k++) {
            unsigned long long xp0 = pack2(xs0[k]);
            unsigned long long xp1 = pack2(xs1[k]);
            const unsigned long long* w =
                (const unsigned long long*)&sW1[(4 * c + k) * HID];
            #pragma unroll
            for (int p = 0; p < 8; p++) {
                unsigned long long wp = w[p];
                fma2(acc0[p], xp0, wp);
                fma2(acc1[p], xp1, wp);
            }
        }
    }

    #pragma unroll
    for (int p = 0; p < 8; p += 2) {
        float2 a = unpack2(acc0[p]);
        float2 b = unpack2(acc0[p + 1]);
        g_hpreh[row0 * 4 + p / 2] = pack_half4(a.x, a.y, b.x, b.y);
    }
    if (has1) {
        #pragma unroll
        for (int p = 0; p < 8; p += 2) {
            float2 a = unpack2(acc1[p]);
            float2 b = unpack2(acc1[p + 1]);
            g_hpreh[row1 * 4 + p / 2] = pack_half4(a.x, a.y, b.x, b.y);
        }
    }
}

__device__ __forceinline__ void conv_one(const void* __restrict__ src,
                                         const void* __restrict__ dst,
                                         int fmt, int e, int n) {
    int s = load_idx(src, fmt, e, n);
    int d = load_idx(dst, fmt, e, n);
    atomicAdd(&g_deg_out[s], 1);
    int slot = atomicAdd(&g_deg_in[d], 1);
    slot = slot > 8191 ? 8191 : slot;
    g_dslot[e] = (d << 13) | slot;
}

__global__ void __launch_bounds__(256)
k_fused1(const float* __restrict__ X, const float* __restrict__ W1,
         const void* __restrict__ src, const void* __restrict__ dst,
         int ecount, int n, int gemm_blocks) {
    __shared__ float sW1[F_IN * HID];   // gemm role (32 KB)
    __shared__ int shflags[4];
    if ((int)blockIdx.x < gemm_blocks) {
        gemm1_part(X, W1, sW1, blockIdx.x, n);
    } else {
        int fmt = probe_fmt(src, ecount, n, shflags);
        int e = (blockIdx.x - gemm_blocks) * 512 + threadIdx.x;
        if (e < ecount) conv_one(src, dst, fmt, e, n);
        if (e + 256 < ecount) conv_one(src, dst, fmt, e + 256, n);
    }
}

// ---------------- scan (decoupled lookback) + norms + hpreh scale + cleanup ----------------
__global__ void __launch_bounds__(256) k_scan(int n) {
    __shared__ int wsum[8];
    __shared__ int bexcl_s;
    int tid = threadIdx.x, lane = tid & 31, wid = tid >> 5;
    int b = blockIdx.x;
    int i = b * 256 + tid;
    int v = (i < n) ? g_deg_in[i] : 0;
    int s = v;
    #pragma unroll
    for (int off = 1; off < 32; off <<= 1) {
        int t = __shfl_up_sync(0xffffffff, s, off);
        if (lane >= off) s += t;
    }
    if (lane == 31) wsum[wid] = s;
    __syncthreads();

    if (wid == 0) {
        int w = (lane < 8) ? wsum[lane] : 0;
        #pragma unroll
        for (int off = 1; off < 8; off <<= 1) {
            int t = __shfl_up_sync(0xffffffff, w, off);
            if (lane >= off) w += t;
        }
        if (lane < 8) wsum[lane] = w;
        int T = __shfl_sync(0xffffffff, w, 7);

        if (lane == 0) {
            unsigned long long pk =
                ((unsigned long long)((b == 0) ? 2u : 1u) << 32) | (unsigned)T;
            *((volatile unsigned long long*)&g_lb[b]) = pk;
        }
        int running = 0;
        if (b > 0) {
            int tile = b - 1;
            while (true) {
                int idx = tile - lane;
                int flag, val;
                if (idx >= 0) {
                    unsigned long long x;
                    do {
                        x = *((volatile unsigned long long*)&g_lb[idx]);
                        flag = (int)(x >> 32);
                    } while (flag == 0);
                    val = (int)(unsigned)(x & 0xffffffffull);
                } else { flag = 1; val = 0; }
                unsigned mp = __ballot_sync(0xffffffff, flag == 2);
                if (mp) {
                    int first = __ffs(mp) - 1;
                    int contrib = (lane <= first) ? val : 0;
                    #pragma unroll
                    for (int o = 16; o; o >>= 1)
                        contrib += __shfl_xor_sync(0xffffffff, contrib, o);
                    running += contrib;
                    break;
                } else {
                    int contrib = val;
                    #pragma unroll
                    for (int o = 16; o; o >>= 1)
                        contrib += __shfl_xor_sync(0xffffffff, contrib, o);
                    running += contrib;
                    tile -= 32;
                }
            }
            if (lane == 0) {
                unsigned long long pk = (2ull << 32) | (unsigned)(running + T);
                *((volatile unsigned long long*)&g_lb[b]) = pk;
            }
        }
        if (lane == 0) bexcl_s = running;
    }
    __syncthreads();

    int base = bexcl_s + ((wid > 0) ? wsum[wid - 1] : 0);
    if (i < n) {
        g_row_start[i] = base + s - v;
        int dout = g_deg_out[i]; if (dout < 1) dout = 1;
        int din  = v;            if (din  < 1) din  = 1;
        float nsv = rsqrtf((float)dout);
        g_norm_src[i] = nsv;
        g_norm_dst[i] = rsqrtf((float)din);
        g_deg_out[i] = 0;   // self-clean for next replay
        g_deg_in[i]  = 0;
        // scale this node's hpreh row in place (gemm wrote it unscaled)
        #pragma unroll
        for (int q = 0; q < 4; q++) {
            uint2 t = g_hpreh[i * 4 + q];
            float2 f0 = __half22float2(u2h(t.x));
            float2 f1 = __half22float2(u2h(t.y));
            g_hpreh[i * 4 + q] =
                pack_half4(f0.x * nsv, f0.y * nsv, f1.x * nsv, f1.y * nsv);
        }
    }
}

// ---------------- csr fill (byte offsets, 2 edges/thread) + lb cleanup ----------------
__global__ void __launch_bounds__(256)
k_csr(const void* __restrict__ src, int ecount, int n) {
    __shared__ int shflags[4];
    int fmt = probe_fmt(src, ecount, n, shflags);
    int tid = threadIdx.x;
    if (blockIdx.x == 0) {   // self-clean lookback for next replay
        g_lb[tid] = 0ull;
        g_lb[tid + 256] = 0ull;
    }
    int e = blockIdx.x * 512 + tid;
    if (e < ecount) {
        int s  = load_idx(src, fmt, e, n);
        int ps = __ldcs(&g_dslot[e]);
        g_csr[g_row_start[ps >> 13] + (ps & 8191)] = s << 5;
    }
    e += 256;
    if (e < ecount) {
        int s  = load_idx(src, fmt, e, n);
        int ps = __ldcs(&g_dslot[e]);
        g_csr[g_row_start[ps >> 13] + (ps & 8191)] = s << 5;
    }
}

// ---------------- gather-sum: 4 nodes/warp, 8 lanes/node ----------------
// sub = lane&3 (row quarter), grp = (lane>>2)&1 (edge slot), node = lane>>3.
// Main loop: 4 edges/group/iter = 8 edges/node/iter; tail 1 edge/group.
// Reduce: 1 xor level (off=4) serves all four node-octets simultaneously.
__device__ __forceinline__ void gather_sum4(const uint2* __restrict__ table,
                                            int start, int end, int lane,
                                            float& ax, float& ay,
                                            float& az, float& aw) {
    int sub = lane & 3;
    int grp = (lane >> 2) & 1;
    int deg = end - start;
    int main_end = start + (deg & ~7);
    const char* tbl = (const char*)table + sub * 8;

    ax = ay = az = aw = 0.f;
    for (int e = start + 4 * grp; e < main_end; e += 8) {
        int o0 = __ldg(&g_csr[e]);
        int o1 = __ldg(&g_csr[e + 1]);
        int o2 = __ldg(&g_csr[e + 2]);
        int o3 = __ldg(&g_csr[e + 3]);
        uint2 q0 = *(const uint2*)(tbl + o0);
        uint2 q1 = *(const uint2*)(tbl + o1);
        uint2 q2 = *(const uint2*)(tbl + o2);
        uint2 q3 = *(const uint2*)(tbl + o3);
        __half2 hx0 = __hadd2(u2h(q0.x), u2h(q1.x));
        __half2 hx1 = __hadd2(u2h(q2.x), u2h(q3.x));
        __half2 hy0 = __hadd2(u2h(q0.y), u2h(q1.y));
        __half2 hy1 = __hadd2(u2h(q2.y), u2h(q3.y));
        float2 f0 = __half22float2(hx0);
        float2 f1 = __half22float2(hx1);
        float2 g0 = __half22float2(hy0);
        float2 g1 = __half22float2(hy1);
        ax += f0.x + f1.x; ay += f0.y + f1.y;
        az += g0.x + g1.x; aw += g0.y + g1.y;
    }
    for (int e = main_end + grp; e < end; e += 2) {
        int o0 = __ldg(&g_csr[e]);
        uint2 q0 = *(const uint2*)(tbl + o0);
        float2 f0 = __half22float2(u2h(q0.x));
        float2 g0 = __half22float2(u2h(q0.y));
        ax += f0.x; ay += f0.y; az += g0.x; aw += g0.y;
    }
    // combine the 2 groups within each 8-lane node-octet
    ax += __shfl_xor_sync(0xffffffff, ax, 4);
    ay += __shfl_xor_sync(0xffffffff, ay, 4);
    az += __shfl_xor_sync(0xffffffff, az, 4);
    aw += __shfl_xor_sync(0xffffffff, aw, 4);
}

// ---------------- SpMM stage 1 (4 nodes per warp) ----------------
__global__ void __launch_bounds__(256)
k_spmm1(const float* __restrict__ b1, int n, int ecount) {
    int tid = threadIdx.x;
    int lane = tid & 31;
    int w = (blockIdx.x * 256 + tid) >> 5;     // warp index
    int v = 4 * w + (lane >> 3);               // this octet's node
    bool active = (v < n);

    int start = 0, end = 0;
    if (active) {
        start = g_row_start[v];
        end = (v + 1 < n) ? g_row_start[v + 1] : ecount;
    }
    float ax, ay, az, aw;
    gather_sum4(g_hpreh, start, end, lane, ax, ay, az, aw);

    if ((lane & 4) == 0 && active) {
        int sub = lane & 3;
        float nd = g_norm_dst[v];
        float ns = g_norm_src[v];
        float4 bb = ((const float4*)b1)[sub];
        float rx = fmaxf(ax * nd + bb.x, 0.f) * ns;
        float ry = fmaxf(ay * nd + bb.y, 0.f) * ns;
        float rz = fmaxf(az * nd + bb.z, 0.f) * ns;
        float rw = fmaxf(aw * nd + bb.w, 0.f) * ns;
        g_hmidh[v * 4 + sub] = pack_half4(rx, ry, rz, rw);
    }
}

// ---------------- SpMM stage 2 + GEMM2 (4 nodes per warp) ----------------
__global__ void __launch_bounds__(256)
k_spmm2g2(const float* __restrict__ W2, const float* __restrict__ b2,
          float* __restrict__ out, int n, int ecount) {
    __shared__ float sW2[HID * NLAB];
    __shared__ float sb2[NLAB];
    int tid = threadIdx.x;  // 256
    for (int i = tid; i < HID * NLAB; i += 256) sW2[i] = W2[i];
    if (tid < NLAB) sb2[tid] = b2[tid];
    __syncthreads();

    int lane = tid & 31;
    int w = (blockIdx.x * 256 + tid) >> 5;
    int v = 4 * w + (lane >> 3);
    bool active = (v < n);

    int start = 0, end = 0;
    if (active) {
        start = g_row_start[v];
        end = (v + 1 < n) ? g_row_start[v + 1] : ecount;
    }
    float ax, ay, az, aw;
    gather_sum4(g_hmidh, start, end, lane, ax, ay, az, aw);

    // broadcast this octet's 16 h values (holders: lanes base+0..base+3)
    float nd = active ? g_norm_dst[v] : 0.f;
    int base = lane & 24;
    float h[HID];
    #pragma unroll
    for (int s = 0; s < 4; s++) {
        h[4 * s + 0] = __shfl_sync(0xffffffff, ax, base + s) * nd;
        h[4 * s + 1] = __shfl_sync(0xffffffff, ay, base + s) * nd;
        h[4 * s + 2] = __shfl_sync(0xffffffff, az, base + s) * nd;
        h[4 * s + 3] = __shfl_sync(0xffffffff, aw, base + s) * nd;
    }
    if (!active) return;
    int l8 = lane & 7;
    float acc[8];
    #pragma unroll
    for (int c = 0; c < 8; c++) acc[c] = sb2[l8 + 8 * c];
    #pragma unroll
    for (int k = 0; k < HID; k++) {
        float hk = h[k];
        const float* wrow = &sW2[k * NLAB + l8];
        #pragma unroll
        for (int c = 0; c < 8; c++) acc[c] += hk * wrow[8 * c];
    }
    float* o = out + v * NLAB + l8;
    #pragma unroll
    for (int c = 0; c < 8; c++) o[8 * c] = acc[c];
}

// ---------------- launch ----------------
extern "C" void kernel_launch(void* const* d_in, const int* in_sizes, int n_in,
                              void* d_out, int out_size) {
    int n = out_size / NLAB;
    if (n > NMAX) n = NMAX;

    // Identify inputs by element-count signature.
    int idx_X = -1, idx_W1 = -1, idx_b1 = -1, idx_W2 = -1, idx_b2 = -1;
    int idx_e1 = -1, idx_e2 = -1;
    for (int i = 0; i < n_in; i++) {
        int sz = in_sizes[i];
        if (sz == n * F_IN)            idx_X = i;
        else if (sz == F_IN * HID)     idx_W1 = i;
        else if (sz == HID)            idx_b1 = i;
        else if (sz == HID * NLAB)     idx_W2 = i;
        else if (sz == NLAB)           idx_b2 = i;
        else if (idx_e1 < 0)           idx_e1 = i;
        else                           idx_e2 = i;
    }

    // src/dst by ordering convention (see round-3 notes).
    int idx_src, idx_dst;
    if (idx_e1 > idx_X) { idx_src = idx_e1; idx_dst = idx_e2; }
    else                { idx_dst = idx_e1; idx_src = idx_e2; }

    const float* X   = (const float*)d_in[idx_X];
    const float* W1  = (const float*)d_in[idx_W1];
    const float* b1  = (const float*)d_in[idx_b1];
    const float* W2  = (const float*)d_in[idx_W2];
    const float* b2  = (const float*)d_in[idx_b2];
    const void*  esrc = d_in[idx_src];
    const void*  edst = d_in[idx_dst];

    int ecount = in_sizes[idx_src];
    if (ecount > EMAX) ecount = EMAX;

    int gemm_blocks = (n + 511) / 512;
    int conv_blocks = (ecount + 511) / 512;

    k_fused1<<<gemm_blocks + conv_blocks, 256>>>(X, W1, esrc, edst,
                                                 ecount, n, gemm_blocks);
    k_scan<<<(n + 255) / 256, 256>>>(n);
    k_csr<<<(ecount + 511) / 512, 256>>>(esrc, ecount, n);

    // 4 nodes per warp -> 32 nodes per 256-thread block
    int spmm_blocks = (n + 31) / 32;
    k_spmm1<<<spmm_blocks, 256>>>(b1, n, ecount);
    k_spmm2g2<<<spmm_blocks, 256>>>(W2, b2, (float*)d_out, n, ecount);
}